// round 10
// baseline (speedup 1.0000x reference)
#include <cuda_runtime.h>
#include <math.h>

#define BB   8
#define NPTS 2048
#define KNN  40

// ---------------- scratch (static device globals; no allocations) ------------
static __device__ float g_big[(long)BB * NPTS * NPTS];   // 134 MB: negdist / energy / attn
static __device__ float g_P   [BB * 32  * NPTS];
static __device__ float g_xv  [BB * 128 * NPTS];
static __device__ float g_d   [BB * 128 * NPTS];
static __device__ float g_h0  [BB * 128 * NPTS];         // [x1 ; x2]
static __device__ float g_cat [(long)BB * 512 * NPTS];   // 4 SA outputs
static __device__ float g_At  [BB * NPTS * 64];          // (n,ch) neighbor-term projections
static __device__ float g_Ct  [BB * NPTS * 64];          // (n,ch) center-term projections
static __device__ float g_xx  [BB * NPTS];
static __device__ float g_part[BB * 16 * NPTS];
static __device__ float g_den [BB * NPTS];
static __device__ int   g_idx [BB * NPTS * KNN];
static __device__ float g_Wa  [64 * 64];
static __device__ float g_Wd  [64 * 64];

// ---------------- helpers ----------------------------------------------------
__device__ __forceinline__ unsigned fkey(float f) {
    unsigned u = __float_as_uint(f);
    return (u & 0x80000000u) ? ~u : (u | 0x80000000u);
}
__device__ __forceinline__ float unfkey(unsigned k) {
    unsigned u = (k & 0x80000000u) ? (k & 0x7FFFFFFFu) : ~k;
    return __uint_as_float(u);
}

// ---------------- prep: A1/C1 from x, w1 -------------------------------------
__global__ void prep1_kernel(const float* __restrict__ x, const float* __restrict__ w1) {
    int t = blockIdx.x * 256 + threadIdx.x;
    if (t >= BB * NPTS * 64) return;
    int ch = t & 63;
    int pn = t >> 6;
    const float* xp = x + (long)pn * 3;
    float x0 = xp[0], x1 = xp[1], x2 = xp[2];
    const float* w = w1 + ch * 6;
    float a = w[0] * x0 + w[1] * x1 + w[2] * x2;
    float c = w[3] * x0 + w[4] * x1 + w[5] * x2;
    g_At[t] = a;
    g_Ct[t] = c - a;
}

__global__ void xx3_kernel(const float* __restrict__ x) {
    int i = blockIdx.x * 256 + threadIdx.x;
    if (i >= BB * NPTS) return;
    const float* p = x + (long)i * 3;
    float s = p[0] * p[0];
    s = fmaf(p[1], p[1], s);
    s = fmaf(p[2], p[2], s);
    g_xx[i] = s;
}

__global__ void xx64_kernel() {
    int i = blockIdx.x * 256 + threadIdx.x;
    if (i >= BB * NPTS) return;
    int b = i >> 11, n = i & (NPTS - 1);
    const float* p = g_h0 + (long)b * 128 * NPTS + n;
    float s = 0.f;
#pragma unroll
    for (int c = 0; c < 64; ++c) { float v = p[(long)c * NPTS]; s = fmaf(v, v, s); }
    g_xx[i] = s;
}

__global__ void wsplit_kernel(const float* __restrict__ w3) {
    int t = blockIdx.x * 256 + threadIdx.x;
    if (t >= 4096) return;
    int o = t >> 6, c = t & 63;
    float a = w3[o * 128 + c];
    g_Wa[t] = a;
    g_Wd[t] = w3[o * 128 + 64 + c] - a;
}

// ---------------- Gram kernel: C[r,c] = sum_k P[k,r]*P[k,c] ------------------
// NEG: out = 2*acc - xx[r] - xx[c]  (neg squared distance). Writes g_big.
template <bool NEG>
__global__ __launch_bounds__(256) void gram_kernel(const float* __restrict__ P,
                                                   long pStride, int sK, int sN, int K) {
    __shared__ float As[16][64];
    __shared__ float Bs[16][64];
    int t = threadIdx.x, b = blockIdx.z;
    int n0 = blockIdx.y * 64, m0 = blockIdx.x * 64;
    const float* Pb = P + (long)b * pStride;
    int lK = t >> 4, lN = (t & 15) * 4;
    int ty = t >> 4, tx = t & 15;
    float acc[4][4] = {};
    for (int k0 = 0; k0 < K; k0 += 16) {
        __syncthreads();
        int kk = k0 + lK;
        if (kk < K) {
            long ro = (long)kk * sK;
#pragma unroll
            for (int q = 0; q < 4; ++q) {
                As[lK][lN + q] = Pb[ro + (long)(n0 + lN + q) * sN];
                Bs[lK][lN + q] = Pb[ro + (long)(m0 + lN + q) * sN];
            }
        } else {
#pragma unroll
            for (int q = 0; q < 4; ++q) { As[lK][lN + q] = 0.f; Bs[lK][lN + q] = 0.f; }
        }
        __syncthreads();
#pragma unroll
        for (int k = 0; k < 16; ++k) {
            float a0 = As[k][ty], a1 = As[k][ty + 16], a2 = As[k][ty + 32], a3 = As[k][ty + 48];
            float h0 = Bs[k][tx], h1 = Bs[k][tx + 16], h2 = Bs[k][tx + 32], h3 = Bs[k][tx + 48];
            acc[0][0] = fmaf(a0, h0, acc[0][0]); acc[0][1] = fmaf(a0, h1, acc[0][1]);
            acc[0][2] = fmaf(a0, h2, acc[0][2]); acc[0][3] = fmaf(a0, h3, acc[0][3]);
            acc[1][0] = fmaf(a1, h0, acc[1][0]); acc[1][1] = fmaf(a1, h1, acc[1][1]);
            acc[1][2] = fmaf(a1, h2, acc[1][2]); acc[1][3] = fmaf(a1, h3, acc[1][3]);
            acc[2][0] = fmaf(a2, h0, acc[2][0]); acc[2][1] = fmaf(a2, h1, acc[2][1]);
            acc[2][2] = fmaf(a2, h2, acc[2][2]); acc[2][3] = fmaf(a2, h3, acc[2][3]);
            acc[3][0] = fmaf(a3, h0, acc[3][0]); acc[3][1] = fmaf(a3, h1, acc[3][1]);
            acc[3][2] = fmaf(a3, h2, acc[3][2]); acc[3][3] = fmaf(a3, h3, acc[3][3]);
        }
    }
    float* out = g_big + (long)b * NPTS * NPTS;
    const float* xxb = g_xx + b * NPTS;
#pragma unroll
    for (int j = 0; j < 4; ++j)
#pragma unroll
        for (int i = 0; i < 4; ++i) {
            int r = n0 + ty + 16 * j, c = m0 + tx + 16 * i;
            float v = acc[j][i];
            if (NEG) v = 2.f * v - xxb[r] - xxb[c];
            out[(long)r * NPTS + c] = v;
        }
}

// ---------------- top-k (k=40) per row, ties -> lowest index -----------------
__global__ __launch_bounds__(256) void topk_kernel() {
    __shared__ float vals[NPTS];
    __shared__ float rv[8];
    __shared__ int ri[8];
    long row = (long)blockIdx.y * NPTS + blockIdx.x;
    const float* p = g_big + row * NPTS;
    int t = threadIdx.x;
#pragma unroll
    for (int q = 0; q < 8; ++q) vals[t + 256 * q] = p[t + 256 * q];
    __syncthreads();
    int* out = g_idx + row * KNN;
    for (int it = 0; it < KNN; ++it) {
        float bv = -INFINITY;
        int bi = NPTS;
#pragma unroll
        for (int q = 0; q < 8; ++q) {
            int i = t + 256 * q;
            float v = vals[i];
            if (v > bv) { bv = v; bi = i; }
        }
#pragma unroll
        for (int off = 16; off; off >>= 1) {
            float ov = __shfl_down_sync(0xffffffffu, bv, off);
            int   oi = __shfl_down_sync(0xffffffffu, bi, off);
            if (ov > bv || (ov == bv && oi < bi)) { bv = ov; bi = oi; }
        }
        if ((t & 31) == 0) { rv[t >> 5] = bv; ri[t >> 5] = bi; }
        __syncthreads();
        if (t == 0) {
            float Bv = rv[0]; int Iv = ri[0];
#pragma unroll
            for (int w = 1; w < 8; ++w)
                if (rv[w] > Bv || (rv[w] == Bv && ri[w] < Iv)) { Bv = rv[w]; Iv = ri[w]; }
            out[it] = Iv;
            vals[Iv] = -INFINITY;
        }
        __syncthreads();
    }
}

// ---------------- EdgeConv fused: gather + bn/lrelu + 64x64 GEMM + maxpool ---
__global__ __launch_bounds__(256) void edgeconv_kernel(
    const float* __restrict__ W2,
    const float* __restrict__ g1v, const float* __restrict__ b1v,
    const float* __restrict__ g2v, const float* __restrict__ b2v,
    float* __restrict__ outp, long outStride) {
    __shared__ float W2s[64][64];   // [k][o]
    __shared__ float Hs[64][64];    // [k][col]
    __shared__ unsigned maxs[64][8];
    __shared__ float s1s[64], b1s[64], s2s[64], b2s[64];
    int t = threadIdx.x, b = blockIdx.y, pg = blockIdx.x;
    float rs = 1.0f / sqrtf(1.0f + 1e-5f);
    for (int i = t; i < 4096; i += 256) { int o = i >> 6, k = i & 63; W2s[k][o] = W2[o * 64 + k]; }
    if (t < 64) { s1s[t] = g1v[t] * rs; b1s[t] = b1v[t]; s2s[t] = g2v[t] * rs; b2s[t] = b2v[t]; }
    for (int i = t; i < 512; i += 256) ((unsigned*)maxs)[i] = 0u;
    const int* idxb = g_idx + ((long)b * NPTS + pg * 8) * KNN;
    long abase = (long)b * NPTS * 64;
    int ty = t >> 4, tx = t & 15;
    int lc = t >> 2, q = t & 3;
    for (int ct = 0; ct < 5; ++ct) {
        __syncthreads();
        int cb = ct * 64 + lc;            // 0..319
        int nl = cb / 40;
        int j = idxb[cb];
        int n = pg * 8 + nl;
        const float* Ap = g_At + abase + (long)j * 64;
        const float* Cp = g_Ct + abase + (long)n * 64;
#pragma unroll
        for (int ii = 0; ii < 4; ++ii) {
            int ch = q * 16 + ii * 4;
            float4 av = *(const float4*)(Ap + ch);
            float4 cv = *(const float4*)(Cp + ch);
            float v0 = (av.x + cv.x) * s1s[ch + 0] + b1s[ch + 0]; v0 = v0 > 0.f ? v0 : 0.2f * v0;
            float v1 = (av.y + cv.y) * s1s[ch + 1] + b1s[ch + 1]; v1 = v1 > 0.f ? v1 : 0.2f * v1;
            float v2 = (av.z + cv.z) * s1s[ch + 2] + b1s[ch + 2]; v2 = v2 > 0.f ? v2 : 0.2f * v2;
            float v3 = (av.w + cv.w) * s1s[ch + 3] + b1s[ch + 3]; v3 = v3 > 0.f ? v3 : 0.2f * v3;
            Hs[ch + 0][lc] = v0; Hs[ch + 1][lc] = v1; Hs[ch + 2][lc] = v2; Hs[ch + 3][lc] = v3;
        }
        __syncthreads();
        float acc[4][4] = {};
#pragma unroll
        for (int kk = 0; kk < 64; ++kk) {
            float a0 = W2s[kk][ty], a1 = W2s[kk][ty + 16], a2 = W2s[kk][ty + 32], a3 = W2s[kk][ty + 48];
            float h0 = Hs[kk][tx], h1 = Hs[kk][tx + 16], h2 = Hs[kk][tx + 32], h3 = Hs[kk][tx + 48];
            acc[0][0] = fmaf(a0, h0, acc[0][0]); acc[0][1] = fmaf(a0, h1, acc[0][1]);
            acc[0][2] = fmaf(a0, h2, acc[0][2]); acc[0][3] = fmaf(a0, h3, acc[0][3]);
            acc[1][0] = fmaf(a1, h0, acc[1][0]); acc[1][1] = fmaf(a1, h1, acc[1][1]);
            acc[1][2] = fmaf(a1, h2, acc[1][2]); acc[1][3] = fmaf(a1, h3, acc[1][3]);
            acc[2][0] = fmaf(a2, h0, acc[2][0]); acc[2][1] = fmaf(a2, h1, acc[2][1]);
            acc[2][2] = fmaf(a2, h2, acc[2][2]); acc[2][3] = fmaf(a2, h3, acc[2][3]);
            acc[3][0] = fmaf(a3, h0, acc[3][0]); acc[3][1] = fmaf(a3, h1, acc[3][1]);
            acc[3][2] = fmaf(a3, h2, acc[3][2]); acc[3][3] = fmaf(a3, h3, acc[3][3]);
        }
#pragma unroll
        for (int jj = 0; jj < 4; ++jj)
#pragma unroll
            for (int ii = 0; ii < 4; ++ii) {
                int o = ty + 16 * jj;
                int cb2 = ct * 64 + tx + 16 * ii;
                int nl2 = cb2 / 40;
                float v = acc[jj][ii] * s2s[o] + b2s[o];
                v = v > 0.f ? v : 0.2f * v;
                atomicMax(&maxs[o][nl2], fkey(v));
            }
    }
    __syncthreads();
    for (int i = t; i < 512; i += 256) {
        int o = i >> 3, p = i & 7;
        outp[(long)b * outStride + (long)o * NPTS + pg * 8 + p] = unfkey(maxs[o][p]);
    }
}

// ---------------- softmax over rows of g_big (in place) ----------------------
__global__ __launch_bounds__(256) void softmax_kernel() {
    __shared__ float sh[8];
    long row = (long)blockIdx.y * NPTS + blockIdx.x;
    float* p = g_big + row * NPTS;
    int t = threadIdx.x;
    float r[8];
    float m = -INFINITY;
#pragma unroll
    for (int q = 0; q < 8; ++q) { r[q] = p[t + 256 * q]; m = fmaxf(m, r[q]); }
#pragma unroll
    for (int off = 16; off; off >>= 1) m = fmaxf(m, __shfl_xor_sync(0xffffffffu, m, off));
    if ((t & 31) == 0) sh[t >> 5] = m;
    __syncthreads();
    m = sh[0];
#pragma unroll
    for (int w = 1; w < 8; ++w) m = fmaxf(m, sh[w]);
    float s = 0.f;
#pragma unroll
    for (int q = 0; q < 8; ++q) { r[q] = expf(r[q] - m); s += r[q]; }
#pragma unroll
    for (int off = 16; off; off >>= 1) s += __shfl_xor_sync(0xffffffffu, s, off);
    __syncthreads();
    if ((t & 31) == 0) sh[t >> 5] = s;
    __syncthreads();
    s = sh[0];
#pragma unroll
    for (int w = 1; w < 8; ++w) s += sh[w];
    float inv = 1.0f / s;
#pragma unroll
    for (int q = 0; q < 8; ++q) p[t + 256 * q] = r[q] * inv;
}

// ---------------- deterministic column sums of attn --------------------------
__global__ void colpart_kernel() {
    int m = blockIdx.x * 256 + threadIdx.x;
    int cy = blockIdx.y, b = blockIdx.z;
    const float* p = g_big + (long)b * NPTS * NPTS + (long)cy * 128 * NPTS + m;
    float s = 0.f;
#pragma unroll 8
    for (int r = 0; r < 128; ++r) s += p[(long)r * NPTS];
    g_part[((long)b * 16 + cy) * NPTS + m] = s;
}
__global__ void colred_kernel() {
    int m = blockIdx.x * 256 + threadIdx.x;
    int b = blockIdx.y;
    float s = 1e-9f;
#pragma unroll
    for (int c = 0; c < 16; ++c) s += g_part[((long)b * 16 + c) * NPTS + m];
    g_den[b * NPTS + m] = s;
}

// ---------------- generic GEMM: C = epi(W @ X), 128x128x8 tiles, 8x8 micro ---
// EPI: 0=none 1=+bias 2=xr(d=h-acc/den) 3=sa_out(h+relu(bn(acc+bias))) 4=fuse(leaky(bn))
template <int EPI, bool TOUT>
__global__ __launch_bounds__(256) void gemm_kernel(
    const float* __restrict__ W, long wStride,
    const float* __restrict__ X, long xStride,
    float* __restrict__ Cout, long cStride,
    int M, int N, int K,
    const float* __restrict__ bias,
    const float* __restrict__ gamma, const float* __restrict__ beta,
    const float* __restrict__ den,
    const float* __restrict__ hres, long hStride) {
    __shared__ float As[8][128];
    __shared__ float Bs[8][128];
    int t = threadIdx.x, b = blockIdx.z;
    int m0 = blockIdx.y * 128, n0 = blockIdx.x * 128;
    const float* Wb = W + (long)b * wStride;
    const float* Xb = X + (long)b * xStride;
    int aRow = t >> 1, aK = (t & 1) * 4;
    int bK = t >> 5, bN = (t & 31) * 4;
    int ty = t >> 4, tx = t & 15;
    float acc[8][8] = {};
    for (int k0 = 0; k0 < K; k0 += 8) {
        float4 av = make_float4(0.f, 0.f, 0.f, 0.f);
        if (m0 + aRow < M) av = *(const float4*)(Wb + (long)(m0 + aRow) * K + k0 + aK);
        float4 bv = *(const float4*)(Xb + (long)(k0 + bK) * N + n0 + bN);
        __syncthreads();
        As[aK + 0][aRow] = av.x; As[aK + 1][aRow] = av.y;
        As[aK + 2][aRow] = av.z; As[aK + 3][aRow] = av.w;
        *(float4*)&Bs[bK][bN] = bv;
        __syncthreads();
#pragma unroll
        for (int kk = 0; kk < 8; ++kk) {
            float a[8], h[8];
#pragma unroll
            for (int j = 0; j < 8; ++j) a[j] = As[kk][ty + 16 * j];
#pragma unroll
            for (int i = 0; i < 8; ++i) h[i] = Bs[kk][tx + 16 * i];
#pragma unroll
            for (int j = 0; j < 8; ++j)
#pragma unroll
                for (int i = 0; i < 8; ++i) acc[j][i] = fmaf(a[j], h[i], acc[j][i]);
        }
    }
    const float invs = 1.0f / sqrtf(1.0f + 1e-5f);
#pragma unroll
    for (int j = 0; j < 8; ++j) {
        int o = m0 + ty + 16 * j;
        if (o >= M) continue;
        float bi0 = 0.f, ga0 = 0.f, be0 = 0.f;
        if (EPI == 1 || EPI == 3) bi0 = bias[o];
        if (EPI == 3 || EPI == 4) { ga0 = gamma[o] * invs; be0 = beta[o]; }
#pragma unroll
        for (int i = 0; i < 8; ++i) {
            int n = n0 + tx + 16 * i;
            float v = acc[j][i];
            if (EPI == 1) v += bi0;
            else if (EPI == 2) {
                v = v / den[(long)b * NPTS + n];
                v = hres[(long)b * hStride + (long)o * NPTS + n] - v;
            } else if (EPI == 3) {
                v += bi0;
                v = v * ga0 + be0;
                v = v > 0.f ? v : 0.f;
                v += hres[(long)b * hStride + (long)o * NPTS + n];
            } else if (EPI == 4) {
                v = v * ga0 + be0;
                v = v > 0.f ? v : 0.2f * v;
            }
            if (TOUT) Cout[(long)b * cStride + (long)n * M + o] = v;
            else      Cout[(long)b * cStride + (long)o * N + n] = v;
        }
    }
}

// ---------------- launcher ---------------------------------------------------
extern "C" void kernel_launch(void* const* d_in, const int* in_sizes, int n_in,
                              void* d_out, int out_size) {
    const float* x  = (const float*)d_in[0];
    const float* w1 = (const float*)d_in[1];
    const float* g1 = (const float*)d_in[2];
    const float* b1 = (const float*)d_in[3];
    const float* w2 = (const float*)d_in[4];
    const float* g2 = (const float*)d_in[5];
    const float* b2 = (const float*)d_in[6];
    const float* w3 = (const float*)d_in[7];
    const float* g3 = (const float*)d_in[8];
    const float* b3 = (const float*)d_in[9];
    const float* w4 = (const float*)d_in[10];
    const float* g4 = (const float*)d_in[11];
    const float* b4 = (const float*)d_in[12];
    // d_in[13..15] (w5/g5/b5) unused by reference
    const float* qk = (const float*)d_in[16];
    const float* vw = (const float*)d_in[17];
    const float* vb = (const float*)d_in[18];
    const float* tw = (const float*)d_in[19];
    const float* tb = (const float*)d_in[20];
    const float* sg = (const float*)d_in[21];
    const float* sb = (const float*)d_in[22];
    const float* fw = (const float*)d_in[23];
    const float* fg = (const float*)d_in[24];
    const float* fb = (const float*)d_in[25];
    float* out = (float*)d_out;

    float *pBig, *pP, *pXv, *pD, *pH0, *pCat, *pAt, *pCt, *pWa, *pWd, *pDen;
    cudaGetSymbolAddress((void**)&pBig, g_big);
    cudaGetSymbolAddress((void**)&pP,   g_P);
    cudaGetSymbolAddress((void**)&pXv,  g_xv);
    cudaGetSymbolAddress((void**)&pD,   g_d);
    cudaGetSymbolAddress((void**)&pH0,  g_h0);
    cudaGetSymbolAddress((void**)&pCat, g_cat);
    cudaGetSymbolAddress((void**)&pAt,  g_At);
    cudaGetSymbolAddress((void**)&pCt,  g_Ct);
    cudaGetSymbolAddress((void**)&pWa,  g_Wa);
    cudaGetSymbolAddress((void**)&pWd,  g_Wd);
    cudaGetSymbolAddress((void**)&pDen, g_den);

    dim3 blk(256);

    // ---- EdgeConv 1 ----
    prep1_kernel<<<(BB * NPTS * 64 + 255) / 256, blk>>>(x, w1);
    xx3_kernel<<<(BB * NPTS + 255) / 256, blk>>>(x);
    gram_kernel<true><<<dim3(32, 32, BB), blk>>>(x, (long)NPTS * 3, 1, 3, 3);
    topk_kernel<<<dim3(NPTS, BB), blk>>>();
    edgeconv_kernel<<<dim3(NPTS / 8, BB), blk>>>(w2, g1, b1, g2, b2, pH0, (long)128 * NPTS);

    // ---- EdgeConv 2 ----
    wsplit_kernel<<<16, blk>>>(w3);
    gemm_kernel<0, true><<<dim3(16, 1, BB), blk>>>(pWa, 0, pH0, (long)128 * NPTS,
        pAt, (long)NPTS * 64, 64, NPTS, 64, nullptr, nullptr, nullptr, nullptr, nullptr, 0);
    gemm_kernel<0, true><<<dim3(16, 1, BB), blk>>>(pWd, 0, pH0, (long)128 * NPTS,
        pCt, (long)NPTS * 64, 64, NPTS, 64, nullptr, nullptr, nullptr, nullptr, nullptr, 0);
    xx64_kernel<<<(BB * NPTS + 255) / 256, blk>>>();
    gram_kernel<true><<<dim3(32, 32, BB), blk>>>(pH0, (long)128 * NPTS, NPTS, 1, 64);
    topk_kernel<<<dim3(NPTS, BB), blk>>>();
    edgeconv_kernel<<<dim3(NPTS / 8, BB), blk>>>(w4, g3, b3, g4, b4,
        pH0 + (long)64 * NPTS, (long)128 * NPTS);

    // ---- 4 offset-attention layers ----
    for (int i = 0; i < 4; ++i) {
        const float* hin = (i == 0) ? pH0 : pCat + (long)(i - 1) * 128 * NPTS;
        long hStr = (i == 0) ? (long)128 * NPTS : (long)512 * NPTS;
        gemm_kernel<0, false><<<dim3(16, 1, BB), blk>>>(qk + (long)i * 32 * 128, 0, hin, hStr,
            pP, (long)32 * NPTS, 32, NPTS, 128, nullptr, nullptr, nullptr, nullptr, nullptr, 0);
        gemm_kernel<1, false><<<dim3(16, 1, BB), blk>>>(vw + (long)i * 128 * 128, 0, hin, hStr,
            pXv, (long)128 * NPTS, 128, NPTS, 128, vb + i * 128, nullptr, nullptr, nullptr, nullptr, 0);
        gram_kernel<false><<<dim3(32, 32, BB), blk>>>(pP, (long)32 * NPTS, NPTS, 1, 32);
        softmax_kernel<<<dim3(NPTS, BB), blk>>>();
        colpart_kernel<<<dim3(8, 16, BB), blk>>>();
        colred_kernel<<<dim3(8, BB), blk>>>();
        gemm_kernel<2, false><<<dim3(16, 1, BB), blk>>>(pXv, (long)128 * NPTS,
            pBig, (long)NPTS * NPTS, pD, (long)128 * NPTS, 128, NPTS, NPTS,
            nullptr, nullptr, nullptr, pDen, hin, hStr);
        gemm_kernel<3, false><<<dim3(16, 1, BB), blk>>>(tw + (long)i * 128 * 128, 0,
            pD, (long)128 * NPTS, pCat + (long)i * 128 * NPTS, (long)512 * NPTS,
            128, NPTS, 128, tb + i * 128, sg + i * 128, sb + i * 128, nullptr, hin, hStr);
    }

    // ---- fuse ----
    gemm_kernel<4, false><<<dim3(16, 2, BB), blk>>>(fw, 0, pCat, (long)512 * NPTS,
        out, (long)256 * NPTS, 256, NPTS, 512, nullptr, fg, fb, nullptr, nullptr, 0);
}

// round 11
// speedup vs baseline: 2.1588x; 2.1588x over previous
#include <cuda_runtime.h>
#include <cuda_bf16.h>
#include <math.h>

#define BB   8
#define NPTS 2048
#define KNN  40

// ---------------- scratch (static device globals; no allocations) ------------
static __device__ float g_big[(long)BB * NPTS * NPTS];          // 134 MB: knn neg-dist
static __device__ __nv_bfloat16 g_attnh[(long)BB * NPTS * NPTS];// 67 MB: attn bf16
static __device__ float g_P   [BB * 32  * NPTS];
static __device__ __nv_bfloat16 g_xvh[BB * 128 * NPTS];         // xv bf16
static __device__ float g_d   [BB * 128 * NPTS];
static __device__ float g_h0  [BB * 128 * NPTS];                // [x1 ; x2]
static __device__ float g_cat [(long)BB * 512 * NPTS];          // 4 SA outputs
static __device__ float g_At  [BB * NPTS * 64];
static __device__ float g_Ct  [BB * NPTS * 64];
static __device__ float g_xx  [BB * NPTS];
static __device__ float g_part[(long)BB * 256 * NPTS];          // per-block col partials
static __device__ float g_den [BB * NPTS];
static __device__ int   g_idx [BB * NPTS * KNN];
static __device__ float g_Wa  [64 * 64];
static __device__ float g_Wd  [64 * 64];

// ---------------- helpers ----------------------------------------------------
__device__ __forceinline__ unsigned fkey(float f) {
    unsigned u = __float_as_uint(f);
    return (u & 0x80000000u) ? ~u : (u | 0x80000000u);
}
__device__ __forceinline__ float unfkey(unsigned k) {
    unsigned u = (k & 0x80000000u) ? (k & 0x7FFFFFFFu) : ~k;
    return __uint_as_float(u);
}
__device__ __forceinline__ void cvt_store(float* p, float v) { *p = v; }
__device__ __forceinline__ void cvt_store(__nv_bfloat16* p, float v) { *p = __float2bfloat16(v); }

__device__ __forceinline__ void ldsm4(unsigned& r0, unsigned& r1, unsigned& r2, unsigned& r3,
                                      unsigned addr) {
    asm volatile("ldmatrix.sync.aligned.m8n8.x4.shared.b16 {%0,%1,%2,%3},[%4];"
                 : "=r"(r0), "=r"(r1), "=r"(r2), "=r"(r3) : "r"(addr));
}
__device__ __forceinline__ void ldsm4t(unsigned& r0, unsigned& r1, unsigned& r2, unsigned& r3,
                                       unsigned addr) {
    asm volatile("ldmatrix.sync.aligned.m8n8.x4.trans.shared.b16 {%0,%1,%2,%3},[%4];"
                 : "=r"(r0), "=r"(r1), "=r"(r2), "=r"(r3) : "r"(addr));
}
__device__ __forceinline__ void mma16816(float* c, const unsigned* a, unsigned b0, unsigned b1) {
    asm volatile("mma.sync.aligned.m16n8k16.row.col.f32.bf16.bf16.f32 "
                 "{%0,%1,%2,%3},{%4,%5,%6,%7},{%8,%9},{%0,%1,%2,%3};"
                 : "+f"(c[0]), "+f"(c[1]), "+f"(c[2]), "+f"(c[3])
                 : "r"(a[0]), "r"(a[1]), "r"(a[2]), "r"(a[3]), "r"(b0), "r"(b1));
}

// ---------------- prep: A1/C1 from x, w1 -------------------------------------
__global__ void prep1_kernel(const float* __restrict__ x, const float* __restrict__ w1) {
    int t = blockIdx.x * 256 + threadIdx.x;
    if (t >= BB * NPTS * 64) return;
    int ch = t & 63;
    int pn = t >> 6;
    const float* xp = x + (long)pn * 3;
    float x0 = xp[0], x1 = xp[1], x2 = xp[2];
    const float* w = w1 + ch * 6;
    float a = w[0] * x0 + w[1] * x1 + w[2] * x2;
    float c = w[3] * x0 + w[4] * x1 + w[5] * x2;
    g_At[t] = a;
    g_Ct[t] = c - a;
}

__global__ void xx3_kernel(const float* __restrict__ x) {
    int i = blockIdx.x * 256 + threadIdx.x;
    if (i >= BB * NPTS) return;
    const float* p = x + (long)i * 3;
    float s = p[0] * p[0];
    s = fmaf(p[1], p[1], s);
    s = fmaf(p[2], p[2], s);
    g_xx[i] = s;
}

__global__ void xx64_kernel() {
    int i = blockIdx.x * 256 + threadIdx.x;
    if (i >= BB * NPTS) return;
    int b = i >> 11, n = i & (NPTS - 1);
    const float* p = g_h0 + (long)b * 128 * NPTS + n;
    float s = 0.f;
#pragma unroll
    for (int c = 0; c < 64; ++c) { float v = p[(long)c * NPTS]; s = fmaf(v, v, s); }
    g_xx[i] = s;
}

__global__ void wsplit_kernel(const float* __restrict__ w3) {
    int t = blockIdx.x * 256 + threadIdx.x;
    if (t >= 4096) return;
    int o = t >> 6, c = t & 63;
    float a = w3[o * 128 + c];
    g_Wa[t] = a;
    g_Wd[t] = w3[o * 128 + 64 + c] - a;
}

// ---------------- Gram kernel for KNN: neg sq dist into g_big ----------------
__global__ __launch_bounds__(256) void gram_kernel(const float* __restrict__ P,
                                                   long pStride, int sK, int sN, int K) {
    __shared__ float As[16][64];
    __shared__ float Bs[16][64];
    int t = threadIdx.x, b = blockIdx.z;
    int n0 = blockIdx.y * 64, m0 = blockIdx.x * 64;
    const float* Pb = P + (long)b * pStride;
    int lK = t >> 4, lN = (t & 15) * 4;
    int ty = t >> 4, tx = t & 15;
    float acc[4][4] = {};
    for (int k0 = 0; k0 < K; k0 += 16) {
        __syncthreads();
        int kk = k0 + lK;
        if (kk < K) {
            long ro = (long)kk * sK;
#pragma unroll
            for (int q = 0; q < 4; ++q) {
                As[lK][lN + q] = Pb[ro + (long)(n0 + lN + q) * sN];
                Bs[lK][lN + q] = Pb[ro + (long)(m0 + lN + q) * sN];
            }
        } else {
#pragma unroll
            for (int q = 0; q < 4; ++q) { As[lK][lN + q] = 0.f; Bs[lK][lN + q] = 0.f; }
        }
        __syncthreads();
#pragma unroll
        for (int k = 0; k < 16; ++k) {
            float a0 = As[k][ty], a1 = As[k][ty + 16], a2 = As[k][ty + 32], a3 = As[k][ty + 48];
            float h0 = Bs[k][tx], h1 = Bs[k][tx + 16], h2 = Bs[k][tx + 32], h3 = Bs[k][tx + 48];
            acc[0][0] = fmaf(a0, h0, acc[0][0]); acc[0][1] = fmaf(a0, h1, acc[0][1]);
            acc[0][2] = fmaf(a0, h2, acc[0][2]); acc[0][3] = fmaf(a0, h3, acc[0][3]);
            acc[1][0] = fmaf(a1, h0, acc[1][0]); acc[1][1] = fmaf(a1, h1, acc[1][1]);
            acc[1][2] = fmaf(a1, h2, acc[1][2]); acc[1][3] = fmaf(a1, h3, acc[1][3]);
            acc[2][0] = fmaf(a2, h0, acc[2][0]); acc[2][1] = fmaf(a2, h1, acc[2][1]);
            acc[2][2] = fmaf(a2, h2, acc[2][2]); acc[2][3] = fmaf(a2, h3, acc[2][3]);
            acc[3][0] = fmaf(a3, h0, acc[3][0]); acc[3][1] = fmaf(a3, h1, acc[3][1]);
            acc[3][2] = fmaf(a3, h2, acc[3][2]); acc[3][3] = fmaf(a3, h3, acc[3][3]);
        }
    }
    float* out = g_big + (long)b * NPTS * NPTS;
    const float* xxb = g_xx + b * NPTS;
#pragma unroll
    for (int j = 0; j < 4; ++j)
#pragma unroll
        for (int i = 0; i < 4; ++i) {
            int r = n0 + ty + 16 * j, c = m0 + tx + 16 * i;
            out[(long)r * NPTS + c] = 2.f * acc[j][i] - xxb[r] - xxb[c];
        }
}

// ---------------- radix-select top-k (k=40), ties -> lowest index ------------
__global__ __launch_bounds__(256) void topk_radix_kernel() {
    __shared__ unsigned keys[NPTS];
    __shared__ unsigned hist[256];
    __shared__ unsigned sfx[256];
    __shared__ unsigned sh_B, sh_gt, sh_cnt;
    __shared__ int shm_idx[8];
    int t = threadIdx.x;
    long row = (long)blockIdx.y * NPTS + blockIdx.x;
    const float* p = g_big + row * NPTS;
#pragma unroll
    for (int q = 0; q < 8; ++q) keys[t + 256 * q] = fkey(p[t + 256 * q]);
    unsigned pref = 0;
    int need = KNN;
    for (int pass = 0; pass < 4; ++pass) {
        int shift = 24 - 8 * pass;
        hist[t] = 0;
        __syncthreads();
#pragma unroll
        for (int q = 0; q < 8; ++q) {
            unsigned k = keys[t + 256 * q];
            unsigned top = pass ? (k >> (shift + 8)) : 0u;
            if (top == pref) atomicAdd(&hist[(k >> shift) & 255u], 1u);
        }
        __syncthreads();
        unsigned s = hist[t];
        sfx[t] = s;
        __syncthreads();
        for (int d = 1; d < 256; d <<= 1) {
            unsigned a = (t + d < 256) ? sfx[t + d] : 0u;
            __syncthreads();
            s += a;
            sfx[t] = s;
            __syncthreads();
        }
        unsigned gt = (t < 255) ? sfx[t + 1] : 0u;
        if (gt < (unsigned)need && (unsigned)need <= sfx[t]) { sh_B = (unsigned)t; sh_gt = gt; }
        __syncthreads();
        pref = (pref << 8) | sh_B;
        need -= (int)sh_gt;
        __syncthreads();
    }
    if (t == 0) sh_cnt = 0;
    __syncthreads();
    int* out = g_idx + row * KNN;
#pragma unroll
    for (int q = 0; q < 8; ++q) {
        int i = t + 256 * q;
        if (keys[i] > pref) out[atomicAdd(&sh_cnt, 1u)] = i;
    }
    __syncthreads();
    int base = (int)sh_cnt;
    for (int it = 0; it < need; ++it) {
        int bi = NPTS;
#pragma unroll
        for (int q = 0; q < 8; ++q) {
            int i = t + 256 * q;
            if (keys[i] == pref && i < bi) bi = i;
        }
#pragma unroll
        for (int off = 16; off; off >>= 1) {
            int o = __shfl_down_sync(0xffffffffu, bi, off);
            if (o < bi) bi = o;
        }
        if ((t & 31) == 0) shm_idx[t >> 5] = bi;
        __syncthreads();
        if (t == 0) {
            int I = shm_idx[0];
#pragma unroll
            for (int w = 1; w < 8; ++w) if (shm_idx[w] < I) I = shm_idx[w];
            out[base + it] = I;
            keys[I] = 0u;   // key 0 is unreachable for real floats
        }
        __syncthreads();
    }
}

// ---------------- EdgeConv fused: gather + bn/lrelu + 64x64 GEMM + maxpool ---
__global__ __launch_bounds__(256) void edgeconv_kernel(
    const float* __restrict__ W2,
    const float* __restrict__ g1v, const float* __restrict__ b1v,
    const float* __restrict__ g2v, const float* __restrict__ b2v,
    float* __restrict__ outp, long outStride) {
    __shared__ float W2s[64][64];
    __shared__ float Hs[64][64];
    __shared__ unsigned maxs[64][8];
    __shared__ float s1s[64], b1s[64], s2s[64], b2s[64];
    int t = threadIdx.x, b = blockIdx.y, pg = blockIdx.x;
    float rs = 1.0f / sqrtf(1.0f + 1e-5f);
    for (int i = t; i < 4096; i += 256) { int o = i >> 6, k = i & 63; W2s[k][o] = W2[o * 64 + k]; }
    if (t < 64) { s1s[t] = g1v[t] * rs; b1s[t] = b1v[t]; s2s[t] = g2v[t] * rs; b2s[t] = b2v[t]; }
    for (int i = t; i < 512; i += 256) ((unsigned*)maxs)[i] = 0u;
    const int* idxb = g_idx + ((long)b * NPTS + pg * 8) * KNN;
    long abase = (long)b * NPTS * 64;
    int ty = t >> 4, tx = t & 15;
    int lc = t >> 2, q = t & 3;
    for (int ct = 0; ct < 5; ++ct) {
        __syncthreads();
        int cb = ct * 64 + lc;
        int nl = cb / 40;
        int j = idxb[cb];
        int n = pg * 8 + nl;
        const float* Ap = g_At + abase + (long)j * 64;
        const float* Cp = g_Ct + abase + (long)n * 64;
#pragma unroll
        for (int ii = 0; ii < 4; ++ii) {
            int ch = q * 16 + ii * 4;
            float4 av = *(const float4*)(Ap + ch);
            float4 cv = *(const float4*)(Cp + ch);
            float v0 = (av.x + cv.x) * s1s[ch + 0] + b1s[ch + 0]; v0 = v0 > 0.f ? v0 : 0.2f * v0;
            float v1 = (av.y + cv.y) * s1s[ch + 1] + b1s[ch + 1]; v1 = v1 > 0.f ? v1 : 0.2f * v1;
            float v2 = (av.z + cv.z) * s1s[ch + 2] + b1s[ch + 2]; v2 = v2 > 0.f ? v2 : 0.2f * v2;
            float v3 = (av.w + cv.w) * s1s[ch + 3] + b1s[ch + 3]; v3 = v3 > 0.f ? v3 : 0.2f * v3;
            Hs[ch + 0][lc] = v0; Hs[ch + 1][lc] = v1; Hs[ch + 2][lc] = v2; Hs[ch + 3][lc] = v3;
        }
        __syncthreads();
        float acc[4][4] = {};
#pragma unroll
        for (int kk = 0; kk < 64; ++kk) {
            float a0 = W2s[kk][ty], a1 = W2s[kk][ty + 16], a2 = W2s[kk][ty + 32], a3 = W2s[kk][ty + 48];
            float h0 = Hs[kk][tx], h1 = Hs[kk][tx + 16], h2 = Hs[kk][tx + 32], h3 = Hs[kk][tx + 48];
            acc[0][0] = fmaf(a0, h0, acc[0][0]); acc[0][1] = fmaf(a0, h1, acc[0][1]);
            acc[0][2] = fmaf(a0, h2, acc[0][2]); acc[0][3] = fmaf(a0, h3, acc[0][3]);
            acc[1][0] = fmaf(a1, h0, acc[1][0]); acc[1][1] = fmaf(a1, h1, acc[1][1]);
            acc[1][2] = fmaf(a1, h2, acc[1][2]); acc[1][3] = fmaf(a1, h3, acc[1][3]);
            acc[2][0] = fmaf(a2, h0, acc[2][0]); acc[2][1] = fmaf(a2, h1, acc[2][1]);
            acc[2][2] = fmaf(a2, h2, acc[2][2]); acc[2][3] = fmaf(a2, h3, acc[2][3]);
            acc[3][0] = fmaf(a3, h0, acc[3][0]); acc[3][1] = fmaf(a3, h1, acc[3][1]);
            acc[3][2] = fmaf(a3, h2, acc[3][2]); acc[3][3] = fmaf(a3, h3, acc[3][3]);
        }
#pragma unroll
        for (int jj = 0; jj < 4; ++jj)
#pragma unroll
            for (int ii = 0; ii < 4; ++ii) {
                int o = ty + 16 * jj;
                int cb2 = ct * 64 + tx + 16 * ii;
                int nl2 = cb2 / 40;
                float v = acc[jj][ii] * s2s[o] + b2s[o];
                v = v > 0.f ? v : 0.2f * v;
                atomicMax(&maxs[o][nl2], fkey(v));
            }
    }
    __syncthreads();
    for (int i = t; i < 512; i += 256) {
        int o = i >> 3, p = i & 7;
        outp[(long)b * outStride + (long)o * NPTS + pg * 8 + p] = unfkey(maxs[o][p]);
    }
}

// ---------------- fused energy + softmax + colsum (8 rows/block) -------------
__global__ __launch_bounds__(256) void attn_kernel() {
    __shared__ float As[32][8];
    __shared__ float wsm[8][8];   // [row][warp]
    int t = threadIdx.x, b = blockIdx.y;
    int n0 = blockIdx.x * 8;
    int lane = t & 31, warp = t >> 5;
    const float* Pg = g_P + (long)b * 32 * NPTS;
    { int k = t >> 3, r = t & 7; As[k][r] = Pg[(long)k * NPTS + n0 + r]; }
    __syncthreads();
    float acc[8][8] = {};
    for (int k = 0; k < 32; ++k) {
        float a[8];
#pragma unroll
        for (int r = 0; r < 8; ++r) a[r] = As[k][r];
        const float* Pr = Pg + (long)k * NPTS + t;
#pragma unroll
        for (int i = 0; i < 8; ++i) {
            float bb = Pr[256 * i];
#pragma unroll
            for (int r = 0; r < 8; ++r) acc[r][i] = fmaf(a[r], bb, acc[r][i]);
        }
    }
    // row max
    float rmax[8];
#pragma unroll
    for (int r = 0; r < 8; ++r) {
        float m = acc[r][0];
#pragma unroll
        for (int i = 1; i < 8; ++i) m = fmaxf(m, acc[r][i]);
#pragma unroll
        for (int off = 16; off; off >>= 1) m = fmaxf(m, __shfl_xor_sync(0xffffffffu, m, off));
        if (lane == 0) wsm[r][warp] = m;
    }
    __syncthreads();
#pragma unroll
    for (int r = 0; r < 8; ++r) {
        float m = wsm[r][0];
#pragma unroll
        for (int w = 1; w < 8; ++w) m = fmaxf(m, wsm[r][w]);
        rmax[r] = m;
    }
    __syncthreads();
    // exp + row sum
    float rinv[8];
#pragma unroll
    for (int r = 0; r < 8; ++r) {
        float s = 0.f;
#pragma unroll
        for (int i = 0; i < 8; ++i) { acc[r][i] = __expf(acc[r][i] - rmax[r]); s += acc[r][i]; }
#pragma unroll
        for (int off = 16; off; off >>= 1) s += __shfl_xor_sync(0xffffffffu, s, off);
        if (lane == 0) wsm[r][warp] = s;
    }
    __syncthreads();
#pragma unroll
    for (int r = 0; r < 8; ++r) {
        float s = wsm[r][0];
#pragma unroll
        for (int w = 1; w < 8; ++w) s += wsm[r][w];
        rinv[r] = 1.0f / s;
    }
    // scale, write bf16 attn + column partials (deterministic row order)
    float colp[8] = {};
    __nv_bfloat16* ob = g_attnh + (long)b * NPTS * NPTS;
#pragma unroll
    for (int r = 0; r < 8; ++r) {
        __nv_bfloat16* orow = ob + (long)(n0 + r) * NPTS;
#pragma unroll
        for (int i = 0; i < 8; ++i) {
            float v = acc[r][i] * rinv[r];
            colp[i] += v;
            orow[t + 256 * i] = __float2bfloat16(v);
        }
    }
    float* pp = g_part + ((long)b * 256 + blockIdx.x) * NPTS;
#pragma unroll
    for (int i = 0; i < 8; ++i) pp[t + 256 * i] = colp[i];
}

__global__ void colred256_kernel() {
    int m = blockIdx.x * 256 + threadIdx.x;
    int b = blockIdx.y;
    const float* p = g_part + (long)b * 256 * NPTS + m;
    float s = 1e-9f;
#pragma unroll 8
    for (int j = 0; j < 256; ++j) s += p[(long)j * NPTS];
    g_den[b * NPTS + m] = s;
}

// ---------------- xr via bf16 tensor cores: d = h - (xv@attn)/den ------------
__global__ __launch_bounds__(256) void xr_mma_kernel(const float* __restrict__ hres,
                                                     long hStride) {
    __shared__ __align__(16) __nv_bfloat16 As[2][128 * 40];
    __shared__ __align__(16) __nv_bfloat16 Bs[2][32 * 136];
    int t = threadIdx.x, b = blockIdx.z;
    int n0 = blockIdx.x * 128;
    const __nv_bfloat16* Ag = g_xvh + (long)b * 128 * NPTS;
    const __nv_bfloat16* Bg = g_attnh + (long)b * NPTS * NPTS + n0;
    int lane = t & 31, warp = t >> 5;
    int wm = (warp & 3) * 32, wn = (warp >> 2) * 64;
    int aRow = t >> 2, aCol = (t & 3) * 8;
    int bRow = t >> 4, bCol = (t & 15) * 8;
    float acc[2][8][4] = {};
    int4 aR0, aR1, bR0, bR1;

    // prologue: load k0=0 tile
    aR0 = *(const int4*)(Ag + (long)aRow * NPTS + aCol);
    aR1 = *(const int4*)(Ag + (long)(aRow + 64) * NPTS + aCol);
    bR0 = *(const int4*)(Bg + (long)bRow * NPTS + bCol);
    bR1 = *(const int4*)(Bg + (long)(bRow + 16) * NPTS + bCol);
    *(int4*)(As[0] + aRow * 40 + aCol) = aR0;
    *(int4*)(As[0] + (aRow + 64) * 40 + aCol) = aR1;
    *(int4*)(Bs[0] + bRow * 136 + bCol) = bR0;
    *(int4*)(Bs[0] + (bRow + 16) * 136 + bCol) = bR1;

    int lrow = ((lane >> 3) & 1) * 8 + (lane & 7);
    int lk8 = (lane >> 4) * 8;

    for (int k0 = 0; k0 < NPTS; k0 += 32) {
        int buf = (k0 >> 5) & 1;
        if (k0 + 32 < NPTS) {
            aR0 = *(const int4*)(Ag + (long)aRow * NPTS + k0 + 32 + aCol);
            aR1 = *(const int4*)(Ag + (long)(aRow + 64) * NPTS + k0 + 32 + aCol);
            bR0 = *(const int4*)(Bg + (long)(k0 + 32 + bRow) * NPTS + bCol);
            bR1 = *(const int4*)(Bg + (long)(k0 + 32 + bRow + 16) * NPTS + bCol);
        }
        __syncthreads();
        unsigned aB = (unsigned)__cvta_generic_to_shared(As[buf]);
        unsigned bB = (unsigned)__cvta_generic_to_shared(Bs[buf]);
#pragma unroll
        for (int ks = 0; ks < 2; ++ks) {
            unsigned a[2][4];
#pragma unroll
            for (int mt = 0; mt < 2; ++mt) {
                unsigned ad = aB + (unsigned)(((wm + mt * 16 + lrow) * 40 + ks * 16 + lk8) * 2);
                ldsm4(a[mt][0], a[mt][1], a[mt][2], a[mt][3], ad);
            }
#pragma unroll
            for (int ng = 0; ng < 4; ++ng) {
                unsigned b0, b1, b2, b3;
                unsigned bd = bB + (unsigned)(((ks * 16 + lrow) * 136 + wn + ng * 16 + lk8) * 2);
                ldsm4t(b0, b1, b2, b3, bd);
#pragma unroll
                for (int mt = 0; mt < 2; ++mt) {
                    mma16816(acc[mt][ng * 2], a[mt], b0, b1);
                    mma16816(acc[mt][ng * 2 + 1], a[mt], b2, b3);
                }
            }
        }
        if (k0 + 32 < NPTS) {
            __syncthreads();
            int nb = buf ^ 1;
            *(int4*)(As[nb] + aRow * 40 + aCol) = aR0;
            *(int4*)(As[nb] + (aRow + 64) * 40 + aCol) = aR1;
            *(int4*)(Bs[nb] + bRow * 136 + bCol) = bR0;
            *(int4*)(Bs[nb] + (bRow + 16) * 136 + bCol) = bR1;
        }
    }
    const float* denb = g_den + b * NPTS;
    float* dout = g_d + (long)b * 128 * NPTS;
    const float* hb = hres + (long)b * hStride;
#pragma unroll
    for (int mt = 0; mt < 2; ++mt) {
        int r0 = wm + mt * 16 + (lane >> 2);
#pragma unroll
        for (int nt = 0; nt < 8; ++nt) {
            int m = n0 + wn + nt * 8 + (lane & 3) * 2;
            float2 dv = *(const float2*)(denb + m);
            float2 h0 = *(const float2*)(hb + (long)r0 * NPTS + m);
            float2 h1 = *(const float2*)(hb + (long)(r0 + 8) * NPTS + m);
            float* a4 = acc[mt][nt];
            float2 o0, o1;
            o0.x = h0.x - a4[0] / dv.x;
            o0.y = h0.y - a4[1] / dv.y;
            o1.x = h1.x - a4[2] / dv.x;
            o1.y = h1.y - a4[3] / dv.y;
            *(float2*)(dout + (long)r0 * NPTS + m) = o0;
            *(float2*)(dout + (long)(r0 + 8) * NPTS + m) = o1;
        }
    }
}

// ---------------- generic GEMM: C = epi(W @ X), 128x128x8 tiles, 8x8 micro ---
// EPI: 0=none 1=+bias 3=sa_out(h+relu(bn(acc+bias))) 4=fuse(leaky(bn))
template <int EPI, bool TOUT, typename OutT>
__global__ __launch_bounds__(256) void gemm_kernel(
    const float* __restrict__ W, long wStride,
    const float* __restrict__ X, long xStride,
    OutT* __restrict__ Cout, long cStride,
    int M, int N, int K,
    const float* __restrict__ bias,
    const float* __restrict__ gamma, const float* __restrict__ beta,
    const float* __restrict__ hres, long hStride) {
    __shared__ float As[8][128];
    __shared__ float Bs[8][128];
    int t = threadIdx.x, b = blockIdx.z;
    int m0 = blockIdx.y * 128, n0 = blockIdx.x * 128;
    const float* Wb = W + (long)b * wStride;
    const float* Xb = X + (long)b * xStride;
    int aRow = t >> 1, aK = (t & 1) * 4;
    int bK = t >> 5, bN = (t & 31) * 4;
    int ty = t >> 4, tx = t & 15;
    float acc[8][8] = {};
    for (int k0 = 0; k0 < K; k0 += 8) {
        float4 av = make_float4(0.f, 0.f, 0.f, 0.f);
        if (m0 + aRow < M) av = *(const float4*)(Wb + (long)(m0 + aRow) * K + k0 + aK);
        float4 bv = *(const float4*)(Xb + (long)(k0 + bK) * N + n0 + bN);
        __syncthreads();
        As[aK + 0][aRow] = av.x; As[aK + 1][aRow] = av.y;
        As[aK + 2][aRow] = av.z; As[aK + 3][aRow] = av.w;
        *(float4*)&Bs[bK][bN] = bv;
        __syncthreads();
#pragma unroll
        for (int kk = 0; kk < 8; ++kk) {
            float a[8], h[8];
#pragma unroll
            for (int j = 0; j < 8; ++j) a[j] = As[kk][ty + 16 * j];
#pragma unroll
            for (int i = 0; i < 8; ++i) h[i] = Bs[kk][tx + 16 * i];
#pragma unroll
            for (int j = 0; j < 8; ++j)
#pragma unroll
                for (int i = 0; i < 8; ++i) acc[j][i] = fmaf(a[j], h[i], acc[j][i]);
        }
    }
    const float invs = 1.0f / sqrtf(1.0f + 1e-5f);
#pragma unroll
    for (int j = 0; j < 8; ++j) {
        int o = m0 + ty + 16 * j;
        if (o >= M) continue;
        float bi0 = 0.f, ga0 = 0.f, be0 = 0.f;
        if (EPI == 1 || EPI == 3) bi0 = bias[o];
        if (EPI == 3 || EPI == 4) { ga0 = gamma[o] * invs; be0 = beta[o]; }
#pragma unroll
        for (int i = 0; i < 8; ++i) {
            int n = n0 + tx + 16 * i;
            float v = acc[j][i];
            if (EPI == 1) v += bi0;
            else if (EPI == 3) {
                v += bi0;
                v = v * ga0 + be0;
                v = v > 0.f ? v : 0.f;
                v += hres[(long)b * hStride + (long)o * NPTS + n];
            } else if (EPI == 4) {
                v = v * ga0 + be0;
                v = v > 0.f ? v : 0.2f * v;
            }
            if (TOUT) cvt_store(&Cout[(long)b * cStride + (long)n * M + o], v);
            else      cvt_store(&Cout[(long)b * cStride + (long)o * N + n], v);
        }
    }
}

// ---------------- launcher ---------------------------------------------------
extern "C" void kernel_launch(void* const* d_in, const int* in_sizes, int n_in,
                              void* d_out, int out_size) {
    const float* x  = (const float*)d_in[0];
    const float* w1 = (const float*)d_in[1];
    const float* g1 = (const float*)d_in[2];
    const float* b1 = (const float*)d_in[3];
    const float* w2 = (const float*)d_in[4];
    const float* g2 = (const float*)d_in[5];
    const float* b2 = (const float*)d_in[6];
    const float* w3 = (const float*)d_in[7];
    const float* g3 = (const float*)d_in[8];
    const float* b3 = (const float*)d_in[9];
    const float* w4 = (const float*)d_in[10];
    const float* g4 = (const float*)d_in[11];
    const float* b4 = (const float*)d_in[12];
    const float* qk = (const float*)d_in[16];
    const float* vw = (const float*)d_in[17];
    const float* vb = (const float*)d_in[18];
    const float* tw = (const float*)d_in[19];
    const float* tb = (const float*)d_in[20];
    const float* sg = (const float*)d_in[21];
    const float* sb = (const float*)d_in[22];
    const float* fw = (const float*)d_in[23];
    const float* fg = (const float*)d_in[24];
    const float* fb = (const float*)d_in[25];
    float* out = (float*)d_out;

    float *pP, *pD, *pH0, *pCat, *pAt, *pCt, *pWa, *pWd;
    __nv_bfloat16* pXvh;
    cudaGetSymbolAddress((void**)&pP,   g_P);
    cudaGetSymbolAddress((void**)&pXvh, g_xvh);
    cudaGetSymbolAddress((void**)&pD,   g_d);
    cudaGetSymbolAddress((void**)&pH0,  g_h0);
    cudaGetSymbolAddress((void**)&pCat, g_cat);
    cudaGetSymbolAddress((void**)&pAt,  g_At);
    cudaGetSymbolAddress((void**)&pCt,  g_Ct);
    cudaGetSymbolAddress((void**)&pWa,  g_Wa);
    cudaGetSymbolAddress((void**)&pWd,  g_Wd);

    dim3 blk(256);

    // ---- EdgeConv 1 ----
    prep1_kernel<<<(BB * NPTS * 64 + 255) / 256, blk>>>(x, w1);
    xx3_kernel<<<(BB * NPTS + 255) / 256, blk>>>(x);
    gram_kernel<<<dim3(32, 32, BB), blk>>>(x, (long)NPTS * 3, 1, 3, 3);
    topk_radix_kernel<<<dim3(NPTS, BB), blk>>>();
    edgeconv_kernel<<<dim3(NPTS / 8, BB), blk>>>(w2, g1, b1, g2, b2, pH0, (long)128 * NPTS);

    // ---- EdgeConv 2 ----
    wsplit_kernel<<<16, blk>>>(w3);
    gemm_kernel<0, true, float><<<dim3(16, 1, BB), blk>>>(pWa, 0, pH0, (long)128 * NPTS,
        pAt, (long)NPTS * 64, 64, NPTS, 64, nullptr, nullptr, nullptr, nullptr, 0);
    gemm_kernel<0, true, float><<<dim3(16, 1, BB), blk>>>(pWd, 0, pH0, (long)128 * NPTS,
        pCt, (long)NPTS * 64, 64, NPTS, 64, nullptr, nullptr, nullptr, nullptr, 0);
    xx64_kernel<<<(BB * NPTS + 255) / 256, blk>>>();
    gram_kernel<<<dim3(32, 32, BB), blk>>>(pH0, (long)128 * NPTS, NPTS, 1, 64);
    topk_radix_kernel<<<dim3(NPTS, BB), blk>>>();
    edgeconv_kernel<<<dim3(NPTS / 8, BB), blk>>>(w4, g3, b3, g4, b4,
        pH0 + (long)64 * NPTS, (long)128 * NPTS);

    // ---- 4 offset-attention layers ----
    for (int i = 0; i < 4; ++i) {
        const float* hin = (i == 0) ? pH0 : pCat + (long)(i - 1) * 128 * NPTS;
        long hStr = (i == 0) ? (long)128 * NPTS : (long)512 * NPTS;
        gemm_kernel<0, false, float><<<dim3(16, 1, BB), blk>>>(qk + (long)i * 32 * 128, 0,
            hin, hStr, pP, (long)32 * NPTS, 32, NPTS, 128, nullptr, nullptr, nullptr, nullptr, 0);
        gemm_kernel<1, false, __nv_bfloat16><<<dim3(16, 1, BB), blk>>>(vw + (long)i * 128 * 128, 0,
            hin, hStr, pXvh, (long)128 * NPTS, 128, NPTS, 128, vb + i * 128,
            nullptr, nullptr, nullptr, 0);
        attn_kernel<<<dim3(NPTS / 8, BB), blk>>>();
        colred256_kernel<<<dim3(NPTS / 256, BB), blk>>>();
        xr_mma_kernel<<<dim3(NPTS / 128, 1, BB), blk>>>(hin, hStr);
        gemm_kernel<3, false, float><<<dim3(16, 1, BB), blk>>>(tw + (long)i * 128 * 128, 0,
            pD, (long)128 * NPTS, pCat + (long)i * 128 * NPTS, (long)512 * NPTS,
            128, NPTS, 128, tb + i * 128, sg + i * 128, sb + i * 128, hin, hStr);
    }

    // ---- fuse ----
    gemm_kernel<4, false, float><<<dim3(16, 2, BB), blk>>>(fw, 0, pCat, (long)512 * NPTS,
        out, (long)256 * NPTS, 256, NPTS, 512, nullptr, fg, fb, nullptr, 0);
}